// round 1
// baseline (speedup 1.0000x reference)
#include <cuda_runtime.h>
#include <math.h>

#define HH 192
#define WWID 192
#define HW 36864
#define DIM 96
#define NHW 47
#define NWW 95
#define NWIN 4465
#define NPOS 32

// ---------------- scratch (device globals; no allocs allowed) ----------------
__device__ float g_fold_r[DIM*HW];
__device__ float g_fold_i[DIM*HW];
__device__ float g_y_r[DIM*HW];
__device__ float g_y_i[DIM*HW];
__device__ float g_t_r[DIM*HW];
__device__ float g_t_i[DIM*HW];
__device__ float g_stats1[4*DIM];
__device__ float g_stats2[4*DIM];
__device__ float g_bn1[4*DIM];   // scale_r, shift_r, scale_i, shift_i
__device__ float g_bn2[4*DIM];

// ---------------- zero scratch ----------------
__global__ void k_zero() {
    int idx = blockIdx.x*256 + threadIdx.x;
    if (idx < DIM*HW) { g_fold_r[idx] = 0.f; g_fold_i[idx] = 0.f; }
    if (idx < 4*DIM)  { g_stats1[idx] = 0.f; g_stats2[idx] = 0.f; }
}

// ---------------- per-window attention (fused gather/qkv/attn/proj/fold) ----
// smem layout (floats):
//   [0,3072)      x real       [3072,6144)  x imag
//   [6144..)      q_r,q_i,k_r,k_i,v_r,v_i  (each 3072)  -> q region reused as "out"
//   [24576,30912) attn real (rows padded to 33)
//   [30912,37248) attn imag
//   [37248,43584) mag
#define ATTN_SMEM (43584*4)

__global__ __launch_bounds__(256) void k_attn(
    const float* __restrict__ xr, const float* __restrict__ xi,
    const float* __restrict__ qwr, const float* __restrict__ qwi,
    const float* __restrict__ pwr, const float* __restrict__ pwi,
    const float* __restrict__ rel)
{
    extern __shared__ float sm[];
    const int SX = 0, SQKV = 6144, SATR = 24576, SATI = 30912, SMG = 37248;
    const int SV = SQKV + 2*6144;

    int tid = threadIdx.x;
    int win = blockIdx.x;
    int wi = win / NWW, wj = win - wi*NWW;
    int h0 = wi*4, w0 = wj*2;

    // gather window
    for (int idx = tid; idx < DIM*NPOS; idx += 256) {
        int c = idx >> 5, n = idx & 31;
        int g = c*HW + (h0 + (n>>2))*WWID + w0 + (n&3);
        sm[SX + idx]        = xr[g];
        sm[SX + 3072 + idx] = xi[g];
    }
    __syncthreads();

    int n = tid & 31, og = tid >> 5;

    // ---- qkv: 288 outputs, 36 per thread-group member, chunks of 4 ----
    for (int ch = 0; ch < 9; ch++) {
        int o0 = og*36 + ch*4;
        float ar[4] = {0,0,0,0}, ai[4] = {0,0,0,0};
        const float* wr0 = qwr + o0*96;
        const float* wi0 = qwi + o0*96;
        #pragma unroll 4
        for (int c = 0; c < 96; c += 4) {
            float4 wrv[4], wiv[4];
            #pragma unroll
            for (int l = 0; l < 4; l++) {
                wrv[l] = *(const float4*)(wr0 + l*96 + c);
                wiv[l] = *(const float4*)(wi0 + l*96 + c);
            }
            #pragma unroll
            for (int cc = 0; cc < 4; cc++) {
                float xrv = sm[SX + (c+cc)*32 + n];
                float xiv = sm[SX + 3072 + (c+cc)*32 + n];
                #pragma unroll
                for (int l = 0; l < 4; l++) {
                    float wr_ = ((const float*)&wrv[l])[cc];
                    float wi_ = ((const float*)&wiv[l])[cc];
                    ar[l] += wr_*xrv - wi_*xiv;
                    ai[l] += wr_*xiv + wi_*xrv;
                }
            }
        }
        #pragma unroll
        for (int l = 0; l < 4; l++) {
            int o = o0 + l;
            int seg = (o >= 192) ? 2 : (o >= 96 ? 1 : 0);
            int oo = o - seg*96;
            sm[SQKV + seg*6144 + oo*32 + n] = ar[l];
            sm[SQKV + seg*6144 + 3072 + oo*32 + n] = ai[l];
        }
    }
    __syncthreads();

    // ---- attn = scale * q . conj(k) + bias ----
    #pragma unroll 1
    for (int k2 = 0; k2 < 24; k2++) {
        int e = tid + 256*k2;
        int hh = e >> 10, r = e & 1023, nn = r >> 5, mm = r & 31;
        float acr = 0.f, aci = 0.f;
        #pragma unroll
        for (int d = 0; d < 16; d++) {
            int cch = hh*16 + d;
            float qr = sm[SQKV + cch*32 + nn];
            float qi = sm[SQKV + 3072 + cch*32 + nn];
            float kr = sm[SQKV + 6144 + cch*32 + mm];
            float ki = sm[SQKV + 6144 + 3072 + cch*32 + mm];
            acr += qr*kr + qi*ki;
            aci += qi*kr - qr*ki;
        }
        acr *= 0.25f; aci *= 0.25f;
        int an = nn>>2, bn = nn&3, am = mm>>2, bm = mm&3;
        acr += rel[hh*105 + 7*(an - am + 7) + (bn - bm + 3)];
        int off = (hh*32 + nn)*33 + mm;
        sm[SATR + off] = acr;
        sm[SATI + off] = aci;
        sm[SMG  + off] = sqrtf(acr*acr + aci*aci);
    }
    __syncthreads();

    // ---- magnitude softmax & complex rescale (192 rows) ----
    if (tid < 192) {
        int base = tid*33;
        float mx = -1e30f;
        #pragma unroll
        for (int m = 0; m < 32; m++) mx = fmaxf(mx, sm[SMG + base + m]);
        float s = 0.f;
        #pragma unroll
        for (int m = 0; m < 32; m++) s += expf(sm[SMG + base + m] - mx);
        float inv = 1.0f / s;
        #pragma unroll
        for (int m = 0; m < 32; m++) {
            float mag = sm[SMG + base + m];
            float f = expf(mag - mx) * inv / (mag + 1e-8f);
            sm[SATR + base + m] *= f;
            sm[SATI + base + m] *= f;
        }
    }
    __syncthreads();

    // ---- out = attn @ v  (write into q region as "out") ----
    for (int ch = 0; ch < 3; ch++) {
        int o0 = og*12 + ch*4;
        int hh = o0 >> 4;                       // uniform within chunk
        float orr[4] = {0,0,0,0}, oii[4] = {0,0,0,0};
        int abase = (hh*32 + n)*33;
        #pragma unroll 4
        for (int m = 0; m < 32; m++) {
            float atr = sm[SATR + abase + m];
            float ati = sm[SATI + abase + m];
            #pragma unroll
            for (int l = 0; l < 4; l++) {
                int o = o0 + l;
                float vr = sm[SV + o*32 + m];
                float vi = sm[SV + 3072 + o*32 + m];
                orr[l] += atr*vr - ati*vi;
                oii[l] += atr*vi + ati*vr;
            }
        }
        #pragma unroll
        for (int l = 0; l < 4; l++) {
            sm[SQKV + (o0+l)*32 + n] = orr[l];
            sm[SQKV + 3072 + (o0+l)*32 + n] = oii[l];
        }
    }
    __syncthreads();

    // ---- proj + atomic fold ----
    int a_ = n >> 2, b_ = n & 3;
    int gpix = (h0 + a_)*WWID + w0 + b_;
    for (int ch = 0; ch < 3; ch++) {
        int o0 = og*12 + ch*4;
        float ar[4] = {0,0,0,0}, ai[4] = {0,0,0,0};
        const float* wr0 = pwr + o0*96;
        const float* wi0 = pwi + o0*96;
        #pragma unroll 4
        for (int c = 0; c < 96; c += 4) {
            float4 wrv[4], wiv[4];
            #pragma unroll
            for (int l = 0; l < 4; l++) {
                wrv[l] = *(const float4*)(wr0 + l*96 + c);
                wiv[l] = *(const float4*)(wi0 + l*96 + c);
            }
            #pragma unroll
            for (int cc = 0; cc < 4; cc++) {
                float xrv = sm[SQKV + (c+cc)*32 + n];
                float xiv = sm[SQKV + 3072 + (c+cc)*32 + n];
                #pragma unroll
                for (int l = 0; l < 4; l++) {
                    float wr_ = ((const float*)&wrv[l])[cc];
                    float wi_ = ((const float*)&wiv[l])[cc];
                    ar[l] += wr_*xrv - wi_*xiv;
                    ai[l] += wr_*xiv + wi_*xrv;
                }
            }
        }
        #pragma unroll
        for (int l = 0; l < 4; l++) {
            atomicAdd(&g_fold_r[(o0+l)*HW + gpix], ar[l]);
            atomicAdd(&g_fold_i[(o0+l)*HW + gpix], ai[l]);
        }
    }
}

// ---------------- y = x + fold/(count+eps); accumulate BN1 stats ------------
__global__ __launch_bounds__(256) void k_combine(
    const float* __restrict__ xr, const float* __restrict__ xi)
{
    int c = blockIdx.y;
    int p0 = blockIdx.x * 4608;
    float s0 = 0.f, s1 = 0.f, s2 = 0.f, s3 = 0.f;
    for (int t = threadIdx.x; t < 4608; t += 256) {
        int p = p0 + t;
        int h = p / WWID, w = p - h*WWID;
        int loh = max(h-7, 0), hih = min(h, 184);
        int cnt_h = hih/4 - (loh+3)/4 + 1;
        int low = max(w-3, 0), hiw = min(w, 188);
        int cnt_w = hiw/2 - (low+1)/2 + 1;
        float inv = 1.0f / ((float)(cnt_h*cnt_w) + 1e-8f);
        int g = c*HW + p;
        float yr = xr[g] + g_fold_r[g]*inv;
        float yi = xi[g] + g_fold_i[g]*inv;
        g_y_r[g] = yr; g_y_i[g] = yi;
        s0 += yr; s1 += yr*yr; s2 += yi; s3 += yi*yi;
    }
    #pragma unroll
    for (int off = 16; off; off >>= 1) {
        s0 += __shfl_xor_sync(0xffffffffu, s0, off);
        s1 += __shfl_xor_sync(0xffffffffu, s1, off);
        s2 += __shfl_xor_sync(0xffffffffu, s2, off);
        s3 += __shfl_xor_sync(0xffffffffu, s3, off);
    }
    __shared__ float rb[8][4];
    int lane = threadIdx.x & 31, wp = threadIdx.x >> 5;
    if (lane == 0) { rb[wp][0]=s0; rb[wp][1]=s1; rb[wp][2]=s2; rb[wp][3]=s3; }
    __syncthreads();
    if (threadIdx.x == 0) {
        float a0=0,a1=0,a2=0,a3=0;
        for (int w2 = 0; w2 < 8; w2++) { a0+=rb[w2][0]; a1+=rb[w2][1]; a2+=rb[w2][2]; a3+=rb[w2][3]; }
        atomicAdd(&g_stats1[c], a0);
        atomicAdd(&g_stats1[96+c], a1);
        atomicAdd(&g_stats1[192+c], a2);
        atomicAdd(&g_stats1[288+c], a3);
    }
}

// ---------------- finalize BN params ----------------
__global__ void k_bnfin(int which,
    const float* __restrict__ gr, const float* __restrict__ br,
    const float* __restrict__ gi, const float* __restrict__ bi)
{
    int c = threadIdx.x;
    if (c >= DIM) return;
    const float* s = which ? g_stats2 : g_stats1;
    float* o = which ? g_bn2 : g_bn1;
    const float invN = 1.0f / (float)HW;
    float mu = s[c]*invN;
    float var = s[96+c]*invN - mu*mu;
    float sc = gr[c]*rsqrtf(var + 1e-5f);
    o[c] = sc; o[96+c] = br[c] - mu*sc;
    mu = s[192+c]*invN;
    var = s[288+c]*invN - mu*mu;
    sc = gi[c]*rsqrtf(var + 1e-5f);
    o[192+c] = sc; o[288+c] = bi[c] - mu*sc;
}

// ---------------- BN1-apply + complex MLP + residual + BN2 stats ------------
// smem: xbn r/i (2*3072), hidden r/i (2*12288) = 30720 floats
#define MLP_SMEM (30720*4)

__global__ __launch_bounds__(256) void k_mlp(
    const float* __restrict__ w1r, const float* __restrict__ w1i,
    const float* __restrict__ w2r, const float* __restrict__ w2i)
{
    extern __shared__ float sm[];
    const int SXR = 0, SXI = 3072, SHR = 6144, SHI = 6144 + 12288;
    int tid = threadIdx.x;
    int p0 = blockIdx.x * 32;

    for (int idx = tid; idx < DIM*32; idx += 256) {
        int c = idx >> 5, nn = idx & 31;
        int g = c*HW + p0 + nn;
        sm[SXR + idx] = g_y_r[g]*g_bn1[c] + g_bn1[96+c];
        sm[SXI + idx] = g_y_i[g]*g_bn1[192+c] + g_bn1[288+c];
    }
    __syncthreads();

    int n = tid & 31, og = tid >> 5;

    // mlp1 (384 out) + cgelu
    for (int ch = 0; ch < 12; ch++) {
        int o0 = og*48 + ch*4;
        float ar[4] = {0,0,0,0}, ai[4] = {0,0,0,0};
        const float* wr0 = w1r + o0*96;
        const float* wi0 = w1i + o0*96;
        #pragma unroll 4
        for (int c = 0; c < 96; c += 4) {
            float4 wrv[4], wiv[4];
            #pragma unroll
            for (int l = 0; l < 4; l++) {
                wrv[l] = *(const float4*)(wr0 + l*96 + c);
                wiv[l] = *(const float4*)(wi0 + l*96 + c);
            }
            #pragma unroll
            for (int cc = 0; cc < 4; cc++) {
                float xrv = sm[SXR + (c+cc)*32 + n];
                float xiv = sm[SXI + (c+cc)*32 + n];
                #pragma unroll
                for (int l = 0; l < 4; l++) {
                    float wr_ = ((const float*)&wrv[l])[cc];
                    float wi_ = ((const float*)&wiv[l])[cc];
                    ar[l] += wr_*xrv - wi_*xiv;
                    ai[l] += wr_*xiv + wi_*xrv;
                }
            }
        }
        #pragma unroll
        for (int l = 0; l < 4; l++) {
            float mag = sqrtf(ar[l]*ar[l] + ai[l]*ai[l]);
            float gel = 0.5f*mag*(1.0f + erff(mag*0.70710678118654752f));
            float f = gel / (mag + 1e-8f);
            sm[SHR + (o0+l)*32 + n] = ar[l]*f;
            sm[SHI + (o0+l)*32 + n] = ai[l]*f;
        }
    }
    __syncthreads();

    // mlp2 (96 out) + residual + BN2 stats
    for (int ch = 0; ch < 3; ch++) {
        int o0 = og*12 + ch*4;
        float ar[4] = {0,0,0,0}, ai[4] = {0,0,0,0};
        const float* wr0 = w2r + o0*384;
        const float* wi0 = w2i + o0*384;
        #pragma unroll 4
        for (int c = 0; c < 384; c += 4) {
            float4 wrv[4], wiv[4];
            #pragma unroll
            for (int l = 0; l < 4; l++) {
                wrv[l] = *(const float4*)(wr0 + l*384 + c);
                wiv[l] = *(const float4*)(wi0 + l*384 + c);
            }
            #pragma unroll
            for (int cc = 0; cc < 4; cc++) {
                float xrv = sm[SHR + (c+cc)*32 + n];
                float xiv = sm[SHI + (c+cc)*32 + n];
                #pragma unroll
                for (int l = 0; l < 4; l++) {
                    float wr_ = ((const float*)&wrv[l])[cc];
                    float wi_ = ((const float*)&wiv[l])[cc];
                    ar[l] += wr_*xrv - wi_*xiv;
                    ai[l] += wr_*xiv + wi_*xrv;
                }
            }
        }
        #pragma unroll
        for (int l = 0; l < 4; l++) {
            int o = o0 + l;
            float tr = sm[SXR + o*32 + n] + ar[l];
            float ti = sm[SXI + o*32 + n] + ai[l];
            g_t_r[o*HW + p0 + n] = tr;
            g_t_i[o*HW + p0 + n] = ti;
            float v0 = tr, v1 = tr*tr, v2 = ti, v3 = ti*ti;
            #pragma unroll
            for (int off = 16; off; off >>= 1) {
                v0 += __shfl_xor_sync(0xffffffffu, v0, off);
                v1 += __shfl_xor_sync(0xffffffffu, v1, off);
                v2 += __shfl_xor_sync(0xffffffffu, v2, off);
                v3 += __shfl_xor_sync(0xffffffffu, v3, off);
            }
            if (n == 0) {
                atomicAdd(&g_stats2[o], v0);
                atomicAdd(&g_stats2[96+o], v1);
                atomicAdd(&g_stats2[192+o], v2);
                atomicAdd(&g_stats2[288+o], v3);
            }
        }
    }
}

// ---------------- BN2-apply -> output (2, B, DIM, H, W) ----------------
__global__ void k_out(float* __restrict__ out) {
    int idx = blockIdx.x*256 + threadIdx.x;
    if (idx >= DIM*HW) return;
    int c = idx / HW;
    out[idx]           = g_t_r[idx]*g_bn2[c]     + g_bn2[96+c];
    out[DIM*HW + idx]  = g_t_i[idx]*g_bn2[192+c] + g_bn2[288+c];
}

// ---------------- launch ----------------
extern "C" void kernel_launch(void* const* d_in, const int* in_sizes, int n_in,
                              void* d_out, int out_size)
{
    const float* xr   = (const float*)d_in[0];
    const float* xi   = (const float*)d_in[1];
    const float* qwr  = (const float*)d_in[2];
    const float* qwi  = (const float*)d_in[3];
    const float* pwr  = (const float*)d_in[4];
    const float* pwi  = (const float*)d_in[5];
    const float* rel  = (const float*)d_in[6];
    const float* w1r  = (const float*)d_in[7];
    const float* w1i  = (const float*)d_in[8];
    const float* w2r  = (const float*)d_in[9];
    const float* w2i  = (const float*)d_in[10];
    const float* n1gr = (const float*)d_in[11];
    const float* n1br = (const float*)d_in[12];
    const float* n1gi = (const float*)d_in[13];
    const float* n1bi = (const float*)d_in[14];
    const float* n2gr = (const float*)d_in[15];
    const float* n2br = (const float*)d_in[16];
    const float* n2gi = (const float*)d_in[17];
    const float* n2bi = (const float*)d_in[18];

    cudaFuncSetAttribute(k_attn, cudaFuncAttributeMaxDynamicSharedMemorySize, ATTN_SMEM);
    cudaFuncSetAttribute(k_mlp,  cudaFuncAttributeMaxDynamicSharedMemorySize, MLP_SMEM);

    k_zero<<<(DIM*HW + 255)/256, 256>>>();
    k_attn<<<NWIN, 256, ATTN_SMEM>>>(xr, xi, qwr, qwi, pwr, pwi, rel);
    k_combine<<<dim3(8, DIM), 256>>>(xr, xi);
    k_bnfin<<<1, 128>>>(0, n1gr, n1br, n1gi, n1bi);
    k_mlp<<<HW/32, 256, MLP_SMEM>>>(w1r, w1i, w2r, w2i);
    k_bnfin<<<1, 128>>>(1, n2gr, n2br, n2gi, n2bi);
    k_out<<<(DIM*HW + 255)/256, 256>>>((float*)d_out);
}

// round 2
// speedup vs baseline: 1.1711x; 1.1711x over previous
#include <cuda_runtime.h>
#include <math.h>

#define HH 192
#define WWID 192
#define HW 36864
#define DIM 96
#define NHW 47
#define NWW 95
#define NWIN 4465
#define NPOS 32

// ---------------- scratch ----------------
__device__ float g_fold_r[DIM*HW];
__device__ float g_fold_i[DIM*HW];
__device__ float g_y_r[DIM*HW];
__device__ float g_y_i[DIM*HW];
__device__ float g_t_r[DIM*HW];
__device__ float g_t_i[DIM*HW];
__device__ float g_stats1[4*DIM];
__device__ float g_stats2[4*DIM];
__device__ float g_bn1[4*DIM];
__device__ float g_bn2[4*DIM];

// packed weights: float4 {wr, wr, -wi, wi} per (o,c)
// qkv: [0,27648)  proj: [27648,36864)  mlp1: [36864,73728)  mlp2: [73728,110592)
#define QOFF  0
#define POFF  27648
#define W1OFF 36864
#define W2OFF 73728
#define NWTOT 110592
__device__ float4 g_wp[NWTOT];

// ---------------- packed f32x2 helpers ----------------
__device__ __forceinline__ unsigned long long pki(unsigned lo, unsigned hi) {
    unsigned long long r;
    asm("mov.b64 %0, {%1, %2};" : "=l"(r) : "r"(lo), "r"(hi));
    return r;
}
__device__ __forceinline__ void fma2(unsigned long long& d, unsigned long long a, unsigned long long b) {
    asm("fma.rn.f32x2 %0, %1, %2, %0;" : "+l"(d) : "l"(a), "l"(b));
}
__device__ __forceinline__ float2 upk(unsigned long long v) {
    float2 f;
    asm("mov.b64 {%0, %1}, %2;" : "=f"(f.x), "=f"(f.y) : "l"(v));
    return f;
}

// stage 384 float4 (4 outputs x 96 channels) from gmem to warp-private smem
__device__ __forceinline__ void stage96(const float4* __restrict__ src, float4* dst, int lane) {
    #pragma unroll
    for (int i = 0; i < 12; i++) dst[lane + 32*i] = src[lane + 32*i];
}

// packed complex GEMM over 96 channels, 4 outputs
// xbase: float offset of input pair array (float2 [c][n]); ws: staged weights [l*96+c]
__device__ __forceinline__ void gemm96(const float* sm, int xbase, int n,
                                       const float4* ws, unsigned long long acc[4]) {
    const uint2* xp = (const uint2*)(sm + xbase);
    const ulonglong2* w = (const ulonglong2*)ws;
    #pragma unroll 2
    for (int c = 0; c < 96; c++) {
        uint2 xv = xp[c*32 + n];
        unsigned long long p1 = pki(xv.x, xv.y);
        unsigned long long p2 = pki(xv.y, xv.x);
        #pragma unroll
        for (int l = 0; l < 4; l++) {
            ulonglong2 wv = w[l*96 + c];
            fma2(acc[l], wv.x, p1);
            fma2(acc[l], wv.y, p2);
        }
    }
}

// ---------------- weight pre-pack ----------------
__global__ void k_pack(const float* __restrict__ qwr, const float* __restrict__ qwi,
                       const float* __restrict__ pwr, const float* __restrict__ pwi,
                       const float* __restrict__ w1r, const float* __restrict__ w1i,
                       const float* __restrict__ w2r, const float* __restrict__ w2i) {
    int idx = blockIdx.x*256 + threadIdx.x;
    if (idx >= NWTOT) return;
    const float *wr, *wi; int j;
    if (idx < POFF)       { wr = qwr; wi = qwi; j = idx; }
    else if (idx < W1OFF) { wr = pwr; wi = pwi; j = idx - POFF; }
    else if (idx < W2OFF) { wr = w1r; wi = w1i; j = idx - W1OFF; }
    else                  { wr = w2r; wi = w2i; j = idx - W2OFF; }
    float a = wr[j], b = wi[j];
    g_wp[idx] = make_float4(a, a, -b, b);
}

// ---------------- zero scratch ----------------
__global__ void k_zero() {
    int idx = blockIdx.x*256 + threadIdx.x;
    if (idx < DIM*HW) { g_fold_r[idx] = 0.f; g_fold_i[idx] = 0.f; }
    if (idx < 4*DIM)  { g_stats1[idx] = 0.f; g_stats2[idx] = 0.f; }
}

// ---------------- attention kernel ----------------
// 384 threads (12 warps). smem floats:
//   SW    [0,18432)      : weight staging (12 warps x 1536)
//   SB    [18432,24768)  : x pairs (6144) -> mag (6336) -> out pairs (6144)
//   SC    [24768,43200)  : q (6144: r/i), k (6144), v (6144)
//   SATR  [43200,49536)  : attn real (rows padded 33)
//   SATI  [49536,55872)  : attn imag
#define ATTN_SMEM (55872*4)

__global__ __launch_bounds__(384) void k_attn(
    const float* __restrict__ xr, const float* __restrict__ xi,
    const float* __restrict__ rel)
{
    extern __shared__ float sm[];
    const int SB = 18432, SC = 24768, SATR = 43200, SATI = 49536, SMG = SB;
    const int SV = SC + 12288;

    int tid = threadIdx.x;
    int win = blockIdx.x;
    int wi = win / NWW, wj = win - wi*NWW;
    int h0 = wi*4, w0 = wj*2;

    int n = tid & 31, og = tid >> 5;
    float4* wslot = (float4*)sm + og*384;

    // gather window into (xr,xi) pairs
    for (int idx = tid; idx < DIM*NPOS; idx += 384) {
        int c = idx >> 5, nn = idx & 31;
        int g = c*HW + (h0 + (nn>>2))*WWID + w0 + (nn&3);
        ((float2*)(sm + SB))[idx] = make_float2(xr[g], xi[g]);
    }
    __syncthreads();

    // ---- qkv: 288 outputs = 12 warps x 24, chunks of 4 ----
    for (int ch = 0; ch < 6; ch++) {
        int o0 = og*24 + ch*4;
        __syncwarp();
        stage96(g_wp + QOFF + o0*96, wslot, n);
        __syncwarp();
        unsigned long long acc[4] = {0,0,0,0};
        gemm96(sm, SB, n, wslot, acc);
        #pragma unroll
        for (int l = 0; l < 4; l++) {
            int o = o0 + l;
            int seg = (o >= 192) ? 2 : (o >= 96 ? 1 : 0);
            int oo = o - seg*96;
            float2 f = upk(acc[l]);
            sm[SC + seg*6144 + oo*32 + n] = f.x;
            sm[SC + seg*6144 + 3072 + oo*32 + n] = f.y;
        }
    }
    __syncthreads();

    // ---- attn = scale * q . conj(k) + bias ----  (mag overwrites x pairs: dead)
    #pragma unroll 1
    for (int k2 = 0; k2 < 16; k2++) {
        int e = tid + 384*k2;
        int hh = e >> 10, r = e & 1023, nn = r >> 5, mm = r & 31;
        float acr = 0.f, aci = 0.f;
        #pragma unroll
        for (int d = 0; d < 16; d++) {
            int cch = hh*16 + d;
            float qr = sm[SC + cch*32 + nn];
            float qi = sm[SC + 3072 + cch*32 + nn];
            float kr = sm[SC + 6144 + cch*32 + mm];
            float ki = sm[SC + 6144 + 3072 + cch*32 + mm];
            acr += qr*kr + qi*ki;
            aci += qi*kr - qr*ki;
        }
        acr *= 0.25f; aci *= 0.25f;
        int an = nn>>2, bn = nn&3, am = mm>>2, bm = mm&3;
        acr += rel[hh*105 + 7*(an - am + 7) + (bn - bm + 3)];
        int off = (hh*32 + nn)*33 + mm;
        sm[SATR + off] = acr;
        sm[SATI + off] = aci;
        sm[SMG  + off] = sqrtf(acr*acr + aci*aci);
    }
    __syncthreads();

    // ---- magnitude softmax & complex rescale (192 rows) ----
    if (tid < 192) {
        int base = tid*33;
        float mx = -1e30f;
        #pragma unroll
        for (int m = 0; m < 32; m++) mx = fmaxf(mx, sm[SMG + base + m]);
        float s = 0.f;
        #pragma unroll
        for (int m = 0; m < 32; m++) s += expf(sm[SMG + base + m] - mx);
        float inv = 1.0f / s;
        #pragma unroll
        for (int m = 0; m < 32; m++) {
            float mag = sm[SMG + base + m];
            float f = expf(mag - mx) * inv / (mag + 1e-8f);
            sm[SATR + base + m] *= f;
            sm[SATI + base + m] *= f;
        }
    }
    __syncthreads();

    // ---- out = attn @ v  -> out pairs into SB (mag dead) ----
    for (int ch = 0; ch < 2; ch++) {
        int o0 = og*8 + ch*4;
        int hh = o0 >> 4;
        float orr[4] = {0,0,0,0}, oii[4] = {0,0,0,0};
        int abase = (hh*32 + n)*33;
        #pragma unroll 4
        for (int m = 0; m < 32; m++) {
            float atr = sm[SATR + abase + m];
            float ati = sm[SATI + abase + m];
            #pragma unroll
            for (int l = 0; l < 4; l++) {
                float vr = sm[SV + (o0+l)*32 + m];
                float vi = sm[SV + 3072 + (o0+l)*32 + m];
                orr[l] += atr*vr - ati*vi;
                oii[l] += atr*vi + ati*vr;
            }
        }
        #pragma unroll
        for (int l = 0; l < 4; l++)
            ((float2*)(sm + SB))[(o0+l)*32 + n] = make_float2(orr[l], oii[l]);
    }
    __syncthreads();

    // ---- proj (packed) + atomic fold ----
    int a_ = n >> 2, b_ = n & 3;
    int gpix = (h0 + a_)*WWID + w0 + b_;
    for (int ch = 0; ch < 2; ch++) {
        int o0 = og*8 + ch*4;
        __syncwarp();
        stage96(g_wp + POFF + o0*96, wslot, n);
        __syncwarp();
        unsigned long long acc[4] = {0,0,0,0};
        gemm96(sm, SB, n, wslot, acc);
        #pragma unroll
        for (int l = 0; l < 4; l++) {
            float2 f = upk(acc[l]);
            atomicAdd(&g_fold_r[(o0+l)*HW + gpix], f.x);
            atomicAdd(&g_fold_i[(o0+l)*HW + gpix], f.y);
        }
    }
}

// ---------------- y = x + fold/(count+eps); BN1 stats ----------------
__global__ __launch_bounds__(256) void k_combine(
    const float* __restrict__ xr, const float* __restrict__ xi)
{
    int c = blockIdx.y;
    int p0 = blockIdx.x * 4608;
    float s0 = 0.f, s1 = 0.f, s2 = 0.f, s3 = 0.f;
    for (int t = threadIdx.x; t < 4608; t += 256) {
        int p = p0 + t;
        int h = p / WWID, w = p - h*WWID;
        int loh = max(h-7, 0), hih = min(h, 184);
        int cnt_h = hih/4 - (loh+3)/4 + 1;
        int low = max(w-3, 0), hiw = min(w, 188);
        int cnt_w = hiw/2 - (low+1)/2 + 1;
        float inv = 1.0f / ((float)(cnt_h*cnt_w) + 1e-8f);
        int g = c*HW + p;
        float yr = xr[g] + g_fold_r[g]*inv;
        float yi = xi[g] + g_fold_i[g]*inv;
        g_y_r[g] = yr; g_y_i[g] = yi;
        s0 += yr; s1 += yr*yr; s2 += yi; s3 += yi*yi;
    }
    #pragma unroll
    for (int off = 16; off; off >>= 1) {
        s0 += __shfl_xor_sync(0xffffffffu, s0, off);
        s1 += __shfl_xor_sync(0xffffffffu, s1, off);
        s2 += __shfl_xor_sync(0xffffffffu, s2, off);
        s3 += __shfl_xor_sync(0xffffffffu, s3, off);
    }
    __shared__ float rb[8][4];
    int lane = threadIdx.x & 31, wp = threadIdx.x >> 5;
    if (lane == 0) { rb[wp][0]=s0; rb[wp][1]=s1; rb[wp][2]=s2; rb[wp][3]=s3; }
    __syncthreads();
    if (threadIdx.x == 0) {
        float a0=0,a1=0,a2=0,a3=0;
        for (int w2 = 0; w2 < 8; w2++) { a0+=rb[w2][0]; a1+=rb[w2][1]; a2+=rb[w2][2]; a3+=rb[w2][3]; }
        atomicAdd(&g_stats1[c], a0);
        atomicAdd(&g_stats1[96+c], a1);
        atomicAdd(&g_stats1[192+c], a2);
        atomicAdd(&g_stats1[288+c], a3);
    }
}

// ---------------- finalize BN params ----------------
__global__ void k_bnfin(int which,
    const float* __restrict__ gr, const float* __restrict__ br,
    const float* __restrict__ gi, const float* __restrict__ bi)
{
    int c = threadIdx.x;
    if (c >= DIM) return;
    const float* s = which ? g_stats2 : g_stats1;
    float* o = which ? g_bn2 : g_bn1;
    const float invN = 1.0f / (float)HW;
    float mu = s[c]*invN;
    float var = s[96+c]*invN - mu*mu;
    float sc = gr[c]*rsqrtf(var + 1e-5f);
    o[c] = sc; o[96+c] = br[c] - mu*sc;
    mu = s[192+c]*invN;
    var = s[288+c]*invN - mu*mu;
    sc = gi[c]*rsqrtf(var + 1e-5f);
    o[192+c] = sc; o[288+c] = bi[c] - mu*sc;
}

// ---------------- BN1-apply + complex MLP + residual + BN2 stats ------------
// 384 threads. smem floats: SW [0,18432) staging; SXP [18432,24576) x pairs;
// SH [24576,49152) hidden pairs
#define MLP_SMEM (49152*4)

__global__ __launch_bounds__(384) void k_mlp()
{
    extern __shared__ float sm[];
    const int SXP = 18432, SH = 24576;
    int tid = threadIdx.x;
    int p0 = blockIdx.x * 32;
    int n = tid & 31, og = tid >> 5;
    float4* wslot = (float4*)sm + og*384;

    for (int idx = tid; idx < DIM*32; idx += 384) {
        int c = idx >> 5, nn = idx & 31;
        int g = c*HW + p0 + nn;
        ((float2*)(sm + SXP))[idx] = make_float2(
            g_y_r[g]*g_bn1[c]     + g_bn1[96+c],
            g_y_i[g]*g_bn1[192+c] + g_bn1[288+c]);
    }
    __syncthreads();

    // mlp1: 384 outputs = 12 warps x 32, chunks of 4; cgelu epilogue
    for (int ch = 0; ch < 8; ch++) {
        int o0 = og*32 + ch*4;
        __syncwarp();
        stage96(g_wp + W1OFF + o0*96, wslot, n);
        __syncwarp();
        unsigned long long acc[4] = {0,0,0,0};
        gemm96(sm, SXP, n, wslot, acc);
        #pragma unroll
        for (int l = 0; l < 4; l++) {
            float2 f = upk(acc[l]);
            float mag = sqrtf(f.x*f.x + f.y*f.y);
            float gel = 0.5f*mag*(1.0f + erff(mag*0.70710678118654752f));
            float fac = gel / (mag + 1e-8f);
            ((float2*)(sm + SH))[(o0+l)*32 + n] = make_float2(f.x*fac, f.y*fac);
        }
    }
    __syncthreads();

    // mlp2: 96 outputs = 12 warps x 8, chunks of 4; 384 channels in 4 sub-blocks
    for (int ch = 0; ch < 2; ch++) {
        int o0 = og*8 + ch*4;
        unsigned long long acc[4] = {0,0,0,0};
        for (int cb = 0; cb < 4; cb++) {
            __syncwarp();
            #pragma unroll
            for (int i = n; i < 384; i += 32) {
                int l = i / 96, cc = i - l*96;
                wslot[i] = g_wp[W2OFF + (o0+l)*384 + cb*96 + cc];
            }
            __syncwarp();
            gemm96(sm, SH + cb*6144, n, wslot, acc);
        }
        #pragma unroll
        for (int l = 0; l < 4; l++) {
            int o = o0 + l;
            float2 f = upk(acc[l]);
            float2 xv = ((float2*)(sm + SXP))[o*32 + n];
            float tr = xv.x + f.x;
            float ti = xv.y + f.y;
            g_t_r[o*HW + p0 + n] = tr;
            g_t_i[o*HW + p0 + n] = ti;
            float v0 = tr, v1 = tr*tr, v2 = ti, v3 = ti*ti;
            #pragma unroll
            for (int off = 16; off; off >>= 1) {
                v0 += __shfl_xor_sync(0xffffffffu, v0, off);
                v1 += __shfl_xor_sync(0xffffffffu, v1, off);
                v2 += __shfl_xor_sync(0xffffffffu, v2, off);
                v3 += __shfl_xor_sync(0xffffffffu, v3, off);
            }
            if (n == 0) {
                atomicAdd(&g_stats2[o], v0);
                atomicAdd(&g_stats2[96+o], v1);
                atomicAdd(&g_stats2[192+o], v2);
                atomicAdd(&g_stats2[288+o], v3);
            }
        }
    }
}

// ---------------- BN2-apply -> output ----------------
__global__ void k_out(float* __restrict__ out) {
    int idx = blockIdx.x*256 + threadIdx.x;
    if (idx >= DIM*HW) return;
    int c = idx / HW;
    out[idx]           = g_t_r[idx]*g_bn2[c]     + g_bn2[96+c];
    out[DIM*HW + idx]  = g_t_i[idx]*g_bn2[192+c] + g_bn2[288+c];
}

// ---------------- launch ----------------
extern "C" void kernel_launch(void* const* d_in, const int* in_sizes, int n_in,
                              void* d_out, int out_size)
{
    const float* xr   = (const float*)d_in[0];
    const float* xi   = (const float*)d_in[1];
    const float* qwr  = (const float*)d_in[2];
    const float* qwi  = (const float*)d_in[3];
    const float* pwr  = (const float*)d_in[4];
    const float* pwi  = (const float*)d_in[5];
    const float* rel  = (const float*)d_in[6];
    const float* w1r  = (const float*)d_in[7];
    const float* w1i  = (const float*)d_in[8];
    const float* w2r  = (const float*)d_in[9];
    const float* w2i  = (const float*)d_in[10];
    const float* n1gr = (const float*)d_in[11];
    const float* n1br = (const float*)d_in[12];
    const float* n1gi = (const float*)d_in[13];
    const float* n1bi = (const float*)d_in[14];
    const float* n2gr = (const float*)d_in[15];
    const float* n2br = (const float*)d_in[16];
    const float* n2gi = (const float*)d_in[17];
    const float* n2bi = (const float*)d_in[18];

    cudaFuncSetAttribute(k_attn, cudaFuncAttributeMaxDynamicSharedMemorySize, ATTN_SMEM);
    cudaFuncSetAttribute(k_mlp,  cudaFuncAttributeMaxDynamicSharedMemorySize, MLP_SMEM);

    k_pack<<<(NWTOT + 255)/256, 256>>>(qwr, qwi, pwr, pwi, w1r, w1i, w2r, w2i);
    k_zero<<<(DIM*HW + 255)/256, 256>>>();
    k_attn<<<NWIN, 384, ATTN_SMEM>>>(xr, xi, rel);
    k_combine<<<dim3(8, DIM), 256>>>(xr, xi);
    k_bnfin<<<1, 128>>>(0, n1gr, n1br, n1gi, n1bi);
    k_mlp<<<HW/32, 384, MLP_SMEM>>>();
    k_bnfin<<<1, 128>>>(1, n2gr, n2br, n2gi, n2bi);
    k_out<<<(DIM*HW + 255)/256, 256>>>((float*)d_out);
}